// round 2
// baseline (speedup 1.0000x reference)
#include <cuda_runtime.h>
#include <math.h>

// Problem constants
#define BB 8
#define NN_ 2048
#define DD 512
#define UU 512

// Scratch (allocation-free: __device__ globals)
__device__ float g_Q[(size_t)BB * NN_ * UU];
__device__ float g_K[(size_t)BB * NN_ * UU];
__device__ float g_V[(size_t)BB * NN_ * UU];
__device__ float g_S[(size_t)BB * NN_ * NN_];

// ---------------------------------------------------------------------------
// Tiled fp32 GEMM: C[M,N] = A[M,K] * op(B) (+ bias)
//   TRANSB=false: B is [K,N] row-major (NN)
//   TRANSB=true : B is [N,K] row-major (NT: C[i,j] = sum_k A[i,k]*B[j,k])
// BM=BN=128, BK=16, 256 threads, 8x8 per-thread micro-tile.
// All dims assumed multiples of tile sizes (true for this problem).
// ---------------------------------------------------------------------------
template <bool TRANSB, bool BIAS>
__global__ void __launch_bounds__(256) gemm_tile(
    const float* __restrict__ A, const float* __restrict__ B,
    const float* __restrict__ bias, float* __restrict__ C,
    int M, int N, int Kdim,
    size_t sA, size_t sB, size_t sC)
{
    A += (size_t)blockIdx.z * sA;
    B += (size_t)blockIdx.z * sB;
    C += (size_t)blockIdx.z * sC;

    __shared__ float As[16][128];
    __shared__ float Bs[16][128];

    const int tx = threadIdx.x;          // 0..15 (n direction)
    const int ty = threadIdx.y;          // 0..15 (m direction)
    const int tid = ty * 16 + tx;        // 0..255
    const int m0 = blockIdx.y * 128;
    const int n0 = blockIdx.x * 128;

    float acc[8][8];
#pragma unroll
    for (int i = 0; i < 8; i++)
#pragma unroll
        for (int j = 0; j < 8; j++) acc[i][j] = 0.0f;

    for (int k0 = 0; k0 < Kdim; k0 += 16) {
        // ---- load A tile (128 rows x 16 k), store transposed As[k][m]
#pragma unroll
        for (int r = 0; r < 2; r++) {
            int f = tid + r * 256;           // 0..511 float4s
            int row = f >> 2;                // 0..127
            int c4  = f & 3;                 // 0..3
            float4 v = *(const float4*)(A + (size_t)(m0 + row) * Kdim + k0 + c4 * 4);
            As[c4 * 4 + 0][row] = v.x;
            As[c4 * 4 + 1][row] = v.y;
            As[c4 * 4 + 2][row] = v.z;
            As[c4 * 4 + 3][row] = v.w;
        }
        // ---- load B tile
        if (TRANSB) {
            // B is [N,K]: tile 128 j-rows x 16 k, store Bs[k][j]
#pragma unroll
            for (int r = 0; r < 2; r++) {
                int f = tid + r * 256;
                int row = f >> 2;            // j within tile
                int c4  = f & 3;
                float4 v = *(const float4*)(B + (size_t)(n0 + row) * Kdim + k0 + c4 * 4);
                Bs[c4 * 4 + 0][row] = v.x;
                Bs[c4 * 4 + 1][row] = v.y;
                Bs[c4 * 4 + 2][row] = v.z;
                Bs[c4 * 4 + 3][row] = v.w;
            }
        } else {
            // B is [K,N]: tile 16 k-rows x 128 n, store Bs[k][n]
#pragma unroll
            for (int r = 0; r < 2; r++) {
                int f = tid + r * 256;
                int row = f >> 5;            // 0..15 (k)
                int c4  = f & 31;            // 0..31
                float4 v = *(const float4*)(B + (size_t)(k0 + row) * N + n0 + c4 * 4);
                *(float4*)&Bs[row][c4 * 4] = v;
            }
        }
        __syncthreads();

#pragma unroll
        for (int k = 0; k < 16; k++) {
            float a[8], b[8];
            *(float4*)(a)     = *(const float4*)&As[k][ty * 8];
            *(float4*)(a + 4) = *(const float4*)&As[k][ty * 8 + 4];
            *(float4*)(b)     = *(const float4*)&Bs[k][tx * 8];
            *(float4*)(b + 4) = *(const float4*)&Bs[k][tx * 8 + 4];
#pragma unroll
            for (int i = 0; i < 8; i++)
#pragma unroll
                for (int j = 0; j < 8; j++)
                    acc[i][j] = fmaf(a[i], b[j], acc[i][j]);
        }
        __syncthreads();
    }

    // ---- epilogue
#pragma unroll
    for (int i = 0; i < 8; i++) {
        int row = m0 + ty * 8 + i;
#pragma unroll
        for (int j = 0; j < 8; j += 4) {
            int col = n0 + tx * 8 + j;
            float4 v;
            v.x = acc[i][j + 0];
            v.y = acc[i][j + 1];
            v.z = acc[i][j + 2];
            v.w = acc[i][j + 3];
            if (BIAS) {
                v.x += bias[col + 0];
                v.y += bias[col + 1];
                v.z += bias[col + 2];
                v.w += bias[col + 3];
            }
            *(float4*)(C + (size_t)row * N + col) = v;
        }
    }
}

// ---------------------------------------------------------------------------
// Row softmax over 2048-wide rows. One block (256 threads) per row.
// ---------------------------------------------------------------------------
__global__ void __launch_bounds__(256) softmax_rows(float* __restrict__ S)
{
    float* p = S + (size_t)blockIdx.x * 2048;
    const int tid = threadIdx.x;

    float4 v0 = ((const float4*)p)[tid];
    float4 v1 = ((const float4*)p)[tid + 256];

    float m = fmaxf(fmaxf(fmaxf(v0.x, v0.y), fmaxf(v0.z, v0.w)),
                    fmaxf(fmaxf(v1.x, v1.y), fmaxf(v1.z, v1.w)));

    __shared__ float red[256];
    red[tid] = m;
    __syncthreads();
    for (int s = 128; s >= 1; s >>= 1) {
        if (tid < s) red[tid] = fmaxf(red[tid], red[tid + s]);
        __syncthreads();
    }
    float rowmax = red[0];
    __syncthreads();

    v0.x = expf(v0.x - rowmax); v0.y = expf(v0.y - rowmax);
    v0.z = expf(v0.z - rowmax); v0.w = expf(v0.w - rowmax);
    v1.x = expf(v1.x - rowmax); v1.y = expf(v1.y - rowmax);
    v1.z = expf(v1.z - rowmax); v1.w = expf(v1.w - rowmax);

    float sum = (v0.x + v0.y + v0.z + v0.w) + (v1.x + v1.y + v1.z + v1.w);
    red[tid] = sum;
    __syncthreads();
    for (int s = 128; s >= 1; s >>= 1) {
        if (tid < s) red[tid] += red[tid + s];
        __syncthreads();
    }
    float inv = 1.0f / red[0];

    v0.x *= inv; v0.y *= inv; v0.z *= inv; v0.w *= inv;
    v1.x *= inv; v1.y *= inv; v1.z *= inv; v1.w *= inv;

    ((float4*)p)[tid]       = v0;
    ((float4*)p)[tid + 256] = v1;
}

// ---------------------------------------------------------------------------
// kernel_launch: inputs order (metadata): inputs, Wq, bq, Wk, bk, Wv, bv
// ---------------------------------------------------------------------------
extern "C" void kernel_launch(void* const* d_in, const int* in_sizes, int n_in,
                              void* d_out, int out_size)
{
    const float* X  = (const float*)d_in[0];
    const float* Wq = (const float*)d_in[1];
    const float* bq = (const float*)d_in[2];
    const float* Wk = (const float*)d_in[3];
    const float* bk = (const float*)d_in[4];
    const float* Wv = (const float*)d_in[5];
    const float* bv = (const float*)d_in[6];
    float* out = (float*)d_out;

    float *Q, *K, *V, *S;
    cudaGetSymbolAddress((void**)&Q, g_Q);
    cudaGetSymbolAddress((void**)&K, g_K);
    cudaGetSymbolAddress((void**)&V, g_V);
    cudaGetSymbolAddress((void**)&S, g_S);

    dim3 blk(16, 16);
    const int MN = BB * NN_;  // 16384 flattened rows

    // Projections: [16384,512] @ [512,512] + bias
    dim3 gproj(UU / 128, MN / 128, 1);
    gemm_tile<false, true><<<gproj, blk>>>(X, Wq, bq, Q, MN, UU, DD, 0, 0, 0);
    gemm_tile<false, true><<<gproj, blk>>>(X, Wk, bk, K, MN, UU, DD, 0, 0, 0);
    gemm_tile<false, true><<<gproj, blk>>>(X, Wv, bv, V, MN, UU, DD, 0, 0, 0);

    // Scores: per batch, S = Q @ K^T  [2048,2048], Kdim = 512 (NT)
    dim3 gsc(NN_ / 128, NN_ / 128, BB);
    gemm_tile<true, false><<<gsc, blk>>>(Q, K, nullptr, S, NN_, NN_, UU,
                                         (size_t)NN_ * UU, (size_t)NN_ * UU,
                                         (size_t)NN_ * NN_);

    // Softmax over each of the 16384 rows of length 2048
    softmax_rows<<<BB * NN_, 256>>>(S);

    // Output: per batch, out = P @ V  [2048,512], Kdim = 2048 (NN)
    dim3 gav(UU / 128, NN_ / 128, BB);
    gemm_tile<false, false><<<gav, blk>>>(S, V, nullptr, out, NN_, UU, NN_,
                                          (size_t)NN_ * NN_, (size_t)NN_ * UU,
                                          (size_t)NN_ * UU);
}

// round 4
// speedup vs baseline: 2.7315x; 2.7315x over previous
#include <cuda_runtime.h>
#include <cuda_bf16.h>
#include <cstdint>
#include <math.h>

#define SEQ 2048
#define BATCH 8
#define DIM 512
#define MTOT (BATCH*SEQ)      // 16384
#define KP_PROJ (3*DIM)       // 1536
#define KP_PV (3*SEQ)         // 6144

// ---------------------------------------------------------------------------
// Scratch (allocation-free __device__ globals)
// ---------------------------------------------------------------------------
__device__ __nv_bfloat16 g_Xa [(size_t)MTOT*KP_PROJ];   // X pattern A (hi,lo,hi)
__device__ __nv_bfloat16 g_Xb [(size_t)MTOT*KP_PROJ];   // X pattern B (hi,hi,lo)
__device__ __nv_bfloat16 g_Wqs[(size_t)DIM*KP_PROJ];    // Wq^T pattern B
__device__ __nv_bfloat16 g_Wks[(size_t)DIM*KP_PROJ];    // Wk^T pattern B
__device__ __nv_bfloat16 g_Wvs[(size_t)DIM*KP_PROJ];    // Wv^T pattern A
__device__ float         g_Qf [(size_t)MTOT*DIM];
__device__ float         g_Kf [(size_t)MTOT*DIM];
__device__ float         g_Vtf[(size_t)DIM*MTOT];       // V^T [512, 16384]
__device__ __nv_bfloat16 g_Qa [(size_t)MTOT*KP_PROJ];   // Q pattern A
__device__ __nv_bfloat16 g_Kb [(size_t)MTOT*KP_PROJ];   // K pattern B
__device__ __nv_bfloat16 g_Vtb[(size_t)BATCH*DIM*KP_PV];// V^T split pattern B, per batch
__device__ float         g_S  [(size_t)BATCH*SEQ*SEQ];  // scores fp32
__device__ __nv_bfloat16 g_Ps [(size_t)BATCH*SEQ*KP_PV];// probs pattern A

// ---------------------------------------------------------------------------
// Helpers
// ---------------------------------------------------------------------------
__device__ __forceinline__ uint32_t smem_u32(const void* p) {
    uint32_t a;
    asm("{ .reg .u64 t; cvta.to.shared.u64 t, %1; cvt.u32.u64 %0, t; }"
        : "=r"(a) : "l"(p));
    return a;
}
__device__ __forceinline__ void cp_async16(uint32_t saddr, const void* gaddr) {
    asm volatile("cp.async.cg.shared.global [%0], [%1], 16;"
                 :: "r"(saddr), "l"(gaddr) : "memory");
}
__device__ __forceinline__ void ldsm_x4(uint32_t& r0, uint32_t& r1,
                                        uint32_t& r2, uint32_t& r3, uint32_t a) {
    asm volatile("ldmatrix.sync.aligned.m8n8.x4.shared.b16 {%0,%1,%2,%3}, [%4];"
                 : "=r"(r0), "=r"(r1), "=r"(r2), "=r"(r3) : "r"(a));
}
__device__ __forceinline__ void mma_bf16(float* d, const uint32_t* a,
                                         const uint32_t* b) {
    asm volatile("mma.sync.aligned.m16n8k16.row.col.f32.bf16.bf16.f32 "
                 "{%0,%1,%2,%3}, {%4,%5,%6,%7}, {%8,%9}, {%0,%1,%2,%3};"
                 : "+f"(d[0]), "+f"(d[1]), "+f"(d[2]), "+f"(d[3])
                 : "r"(a[0]), "r"(a[1]), "r"(a[2]), "r"(a[3]),
                   "r"(b[0]), "r"(b[1]));
}
__device__ __forceinline__ void split2(float x, __nv_bfloat16& h, __nv_bfloat16& l) {
    h = __float2bfloat16(x);
    l = __float2bfloat16(x - __bfloat162float(h));
}
__device__ __forceinline__ uint2 pack4(__nv_bfloat16 a, __nv_bfloat16 b,
                                       __nv_bfloat16 c, __nv_bfloat16 d) {
    __nv_bfloat162 p0; p0.x = a; p0.y = b;
    __nv_bfloat162 p1; p1.x = c; p1.y = d;
    uint2 u; u.x = *(uint32_t*)&p0; u.y = *(uint32_t*)&p1;
    return u;
}

// ---------------------------------------------------------------------------
// bf16 mma.sync GEMM: C[M,N] = A[M,K'] * B^T (B stored [N,K'] K-major)
// BM=BN=128, K-chunk=64 bf16 (128B SW128 rows), 256 thr / 8 warps,
// warp tile 64x32 (2 m-warps x 4 n-warps), cp.async double buffer.
// BIAS_MODE: 0 none, 1 per-column, 2 per-row.
// ---------------------------------------------------------------------------
template <int BIAS_MODE>
__global__ void __launch_bounds__(256) gemm_mma(
    const __nv_bfloat16* __restrict__ A, const __nv_bfloat16* __restrict__ B,
    const float* __restrict__ bias, float* __restrict__ C,
    int ldc, int Kp, long sA, long sB, long sC)
{
    extern __shared__ __align__(16) char smem_raw[];
    uint32_t sraw = smem_u32(smem_raw);
    uint32_t sb = (sraw + 1023u) & ~1023u;
    const uint32_t SA = sb;            // 2 x 16KB A tiles
    const uint32_t SB = sb + 32768;    // 2 x 16KB B tiles

    const int tid = threadIdx.x;
    const int wid = tid >> 5, lid = tid & 31;
    const int wm = wid & 1;            // 0..1 (m)
    const int wn = wid >> 1;           // 0..3 (n)

    A += (size_t)blockIdx.z * sA;
    B += (size_t)blockIdx.z * sB;
    C += (size_t)blockIdx.z * sC;
    const int m0 = blockIdx.y * 128;
    const int n0 = blockIdx.x * 128;

    const char* Abase = (const char*)A + (size_t)m0 * Kp * 2;
    const char* Bbase = (const char*)B + (size_t)n0 * Kp * 2;
    const size_t ldab = (size_t)Kp * 2;
    const int NC = Kp >> 6;

    // cp.async indices: 1024 16B-transfers per tile, 4 per thread
    const int ld_r = tid >> 3;         // base row (0..31) step 32
    const int ld_c = tid & 7;          // 16B chunk 0..7

    // ldmatrix lane geometry
    const int a_r = wm * 64 + ((lid >> 3) & 1) * 8 + (lid & 7); // + mf*16
    const int a_hi = lid >> 4;                                   // k-chunk +0/1
    const int b_n = wn * 32 + ((lid >> 4) & 1) * 8 + (lid & 7); // + p*16
    const int b_hi = (lid >> 3) & 1;

    float acc[4][4][4];
#pragma unroll
    for (int i = 0; i < 4; i++)
#pragma unroll
        for (int j = 0; j < 4; j++)
#pragma unroll
            for (int r = 0; r < 4; r++) acc[i][j][r] = 0.0f;

    // ---- prologue: load chunk 0 into buf 0
    {
        const char* Ac = Abase;
        const char* Bc = Bbase;
#pragma unroll
        for (int i = 0; i < 4; i++) {
            int r = ld_r + i * 32;
            uint32_t so = r * 128 + ((ld_c ^ (r & 7)) * 16);
            cp_async16(SA + so, Ac + (size_t)r * ldab + ld_c * 16);
            cp_async16(SB + so, Bc + (size_t)r * ldab + ld_c * 16);
        }
        asm volatile("cp.async.commit_group;" ::: "memory");
    }

    for (int c = 0; c < NC; c++) {
        const int buf = c & 1;
        if (c + 1 < NC) {
            const int nb = (c + 1) & 1;
            const char* Ac = Abase + (size_t)(c + 1) * 128;
            const char* Bc = Bbase + (size_t)(c + 1) * 128;
#pragma unroll
            for (int i = 0; i < 4; i++) {
                int r = ld_r + i * 32;
                uint32_t so = nb * 16384 + r * 128 + ((ld_c ^ (r & 7)) * 16);
                cp_async16(SA + so, Ac + (size_t)r * ldab + ld_c * 16);
                cp_async16(SB + so, Bc + (size_t)r * ldab + ld_c * 16);
            }
        }
        asm volatile("cp.async.commit_group;" ::: "memory");
        asm volatile("cp.async.wait_group 1;" ::: "memory");
        __syncthreads();

        const uint32_t sa = SA + buf * 16384;
        const uint32_t sbb = SB + buf * 16384;
#pragma unroll
        for (int ks = 0; ks < 4; ks++) {
            uint32_t af[4][4], bf[4][2];
#pragma unroll
            for (int mf = 0; mf < 4; mf++) {
                int r = a_r + mf * 16;
                uint32_t ad = sa + r * 128 + (((ks * 2 + a_hi) ^ (r & 7)) * 16);
                ldsm_x4(af[mf][0], af[mf][1], af[mf][2], af[mf][3], ad);
            }
#pragma unroll
            for (int p = 0; p < 2; p++) {
                int n = b_n + p * 16;
                uint32_t bd = sbb + n * 128 + (((ks * 2 + b_hi) ^ (n & 7)) * 16);
                ldsm_x4(bf[2 * p][0], bf[2 * p][1],
                        bf[2 * p + 1][0], bf[2 * p + 1][1], bd);
            }
#pragma unroll
            for (int mf = 0; mf < 4; mf++)
#pragma unroll
                for (int nf = 0; nf < 4; nf++)
                    mma_bf16(acc[mf][nf], af[mf], bf[nf]);
        }
        __syncthreads();
    }

    // ---- epilogue
    const int g = lid >> 2, t = lid & 3;
#pragma unroll
    for (int mf = 0; mf < 4; mf++) {
#pragma unroll
        for (int half = 0; half < 2; half++) {
            int row = m0 + wm * 64 + mf * 16 + g + half * 8;
            float brow = (BIAS_MODE == 2) ? bias[row] : 0.0f;
#pragma unroll
            for (int nf = 0; nf < 4; nf++) {
                int col = n0 + wn * 32 + nf * 8 + t * 2;
                float2 v;
                v.x = acc[mf][nf][half * 2 + 0];
                v.y = acc[mf][nf][half * 2 + 1];
                if (BIAS_MODE == 1) { v.x += bias[col]; v.y += bias[col + 1]; }
                else if (BIAS_MODE == 2) { v.x += brow; v.y += brow; }
                *(float2*)(C + (size_t)row * ldc + col) = v;
            }
        }
    }
}

// ---------------------------------------------------------------------------
// fp32 [R,C] -> bf16 [R,3C]; PAT 0 = A (hi,lo,hi), 1 = B (hi,hi,lo)
// ---------------------------------------------------------------------------
template <int PAT>
__global__ void __launch_bounds__(256) conv_split(
    const float* __restrict__ in, __nv_bfloat16* __restrict__ out, int C)
{
    int idx = blockIdx.x * 256 + threadIdx.x;         // float4 index
    int cf4 = C >> 2;
    int row = idx / cf4, c4 = idx - row * cf4;
    float4 v = ((const float4*)in)[idx];
    __nv_bfloat16 h0, h1, h2, h3, l0, l1, l2, l3;
    split2(v.x, h0, l0); split2(v.y, h1, l1);
    split2(v.z, h2, l2); split2(v.w, h3, l3);
    size_t ob = (size_t)row * 3 * C + c4 * 4;
    uint2 hp = pack4(h0, h1, h2, h3), lp = pack4(l0, l1, l2, l3);
    *(uint2*)(out + ob)         = hp;
    *(uint2*)(out + ob + C)     = (PAT == 0) ? lp : hp;
    *(uint2*)(out + ob + 2 * C) = (PAT == 0) ? hp : lp;
}

// W [512,512] -> Ws [512 n-rows, 1536] transposed split
template <int PAT>
__global__ void __launch_bounds__(256) conv_wt(
    const float* __restrict__ W, __nv_bfloat16* __restrict__ out)
{
    int t = blockIdx.x * 256 + threadIdx.x;           // 512*512
    int n = t >> 9, k = t & 511;
    __nv_bfloat16 h, l;
    split2(W[(size_t)k * 512 + n], h, l);
    size_t ob = (size_t)n * 1536;
    out[ob + k]        = h;
    out[ob + 512 + k]  = (PAT == 0) ? l : h;
    out[ob + 1024 + k] = (PAT == 0) ? h : l;
}

// Vtf [512, 16384] -> Vtb [8][512][6144] pattern B (batch-segmented m)
__global__ void __launch_bounds__(256) conv_vt(
    const float* __restrict__ Vtf, __nv_bfloat16* __restrict__ Vtb)
{
    int idx = blockIdx.x * 256 + threadIdx.x;         // over 512*4096 float4s
    int u = idx >> 12;
    int m = (idx & 4095) << 2;
    int b = m >> 11, ml = m & 2047;
    float4 v = ((const float4*)Vtf)[idx];
    __nv_bfloat16 h0, h1, h2, h3, l0, l1, l2, l3;
    split2(v.x, h0, l0); split2(v.y, h1, l1);
    split2(v.z, h2, l2); split2(v.w, h3, l3);
    size_t ob = ((size_t)b * DIM + u) * KP_PV + ml;
    uint2 hp = pack4(h0, h1, h2, h3), lp = pack4(l0, l1, l2, l3);
    *(uint2*)(Vtb + ob)        = hp;
    *(uint2*)(Vtb + ob + 2048) = hp;
    *(uint2*)(Vtb + ob + 4096) = lp;
}

// ---------------------------------------------------------------------------
// Softmax over 2048-wide rows, fused split-bf16 output (pattern A)
// ---------------------------------------------------------------------------
__global__ void __launch_bounds__(256) softmax_split(
    const float* __restrict__ S, __nv_bfloat16* __restrict__ Ps)
{
    const float* p = S + (size_t)blockIdx.x * SEQ;
    const int tid = threadIdx.x;

    float4 v0 = ((const float4*)p)[tid];
    float4 v1 = ((const float4*)p)[tid + 256];

    float m = fmaxf(fmaxf(fmaxf(v0.x, v0.y), fmaxf(v0.z, v0.w)),
                    fmaxf(fmaxf(v1.x, v1.y), fmaxf(v1.z, v1.w)));
    __shared__ float red[256];
    red[tid] = m; __syncthreads();
    for (int s = 128; s >= 1; s >>= 1) {
        if (tid < s) red[tid] = fmaxf(red[tid], red[tid + s]);
        __syncthreads();
    }
    float rowmax = red[0]; __syncthreads();

    v0.x = __expf(v0.x - rowmax); v0.y = __expf(v0.y - rowmax);
    v0.z = __expf(v0.z - rowmax); v0.w = __expf(v0.w - rowmax);
    v1.x = __expf(v1.x - rowmax); v1.y = __expf(v1.y - rowmax);
    v1.z = __expf(v1.z - rowmax); v1.w = __expf(v1.w - rowmax);

    float sum = (v0.x + v0.y + v0.z + v0.w) + (v1.x + v1.y + v1.z + v1.w);
    red[tid] = sum; __syncthreads();
    for (int s = 128; s >= 1; s >>= 1) {
        if (tid < s) red[tid] += red[tid + s];
        __syncthreads();
    }
    float inv = 1.0f / red[0];

    size_t ob = (size_t)blockIdx.x * KP_PV;
    __nv_bfloat16 h0, h1, h2, h3, l0, l1, l2, l3;

    split2(v0.x * inv, h0, l0); split2(v0.y * inv, h1, l1);
    split2(v0.z * inv, h2, l2); split2(v0.w * inv, h3, l3);
    {
        uint2 hp = pack4(h0, h1, h2, h3), lp = pack4(l0, l1, l2, l3);
        size_t c = ob + tid * 4;
        *(uint2*)(Ps + c)        = hp;   // pattern A: hi, lo, hi
        *(uint2*)(Ps + c + 2048) = lp;
        *(uint2*)(Ps + c + 4096) = hp;
    }
    split2(v1.x * inv, h0, l0); split2(v1.y * inv, h1, l1);
    split2(v1.z * inv, h2, l2); split2(v1.w * inv, h3, l3);
    {
        uint2 hp = pack4(h0, h1, h2, h3), lp = pack4(l0, l1, l2, l3);
        size_t c = ob + 1024 + tid * 4;
        *(uint2*)(Ps + c)        = hp;
        *(uint2*)(Ps + c + 2048) = lp;
        *(uint2*)(Ps + c + 4096) = hp;
    }
}

// ---------------------------------------------------------------------------
// kernel_launch: inputs = X, Wq, bq, Wk, bk, Wv, bv
// ---------------------------------------------------------------------------
extern "C" void kernel_launch(void* const* d_in, const int* in_sizes, int n_in,
                              void* d_out, int out_size)
{
    const float* X  = (const float*)d_in[0];
    const float* Wq = (const float*)d_in[1];
    const float* bq = (const float*)d_in[2];
    const float* Wk = (const float*)d_in[3];
    const float* bk = (const float*)d_in[4];
    const float* Wv = (const float*)d_in[5];
    const float* bv = (const float*)d_in[6];
    float* out = (float*)d_out;

    __nv_bfloat16 *Xa, *Xb, *Wqs, *Wks, *Wvs, *Qa, *Kb, *Vtb, *Ps;
    float *Qf, *Kf, *Vtf, *S;
    cudaGetSymbolAddress((void**)&Xa,  g_Xa);
    cudaGetSymbolAddress((void**)&Xb,  g_Xb);
    cudaGetSymbolAddress((void**)&Wqs, g_Wqs);
    cudaGetSymbolAddress((void**)&Wks, g_Wks);
    cudaGetSymbolAddress((void**)&Wvs, g_Wvs);
    cudaGetSymbolAddress((void**)&Qf,  g_Qf);
    cudaGetSymbolAddress((void**)&Kf,  g_Kf);
    cudaGetSymbolAddress((void**)&Vtf, g_Vtf);
    cudaGetSymbolAddress((void**)&Qa,  g_Qa);
    cudaGetSymbolAddress((void**)&Kb,  g_Kb);
    cudaGetSymbolAddress((void**)&Vtb, g_Vtb);
    cudaGetSymbolAddress((void**)&S,   g_S);
    cudaGetSymbolAddress((void**)&Ps,  g_Ps);

    const int smemBytes = 1024 + 4 * 16384;  // pad + 2xA + 2xB
    cudaFuncSetAttribute(gemm_mma<0>, cudaFuncAttributeMaxDynamicSharedMemorySize, smemBytes);
    cudaFuncSetAttribute(gemm_mma<1>, cudaFuncAttributeMaxDynamicSharedMemorySize, smemBytes);
    cudaFuncSetAttribute(gemm_mma<2>, cudaFuncAttributeMaxDynamicSharedMemorySize, smemBytes);

    // Split conversions of inputs
    conv_split<0><<<(MTOT * DIM / 4) / 256, 256>>>(X, Xa, DIM);
    conv_split<1><<<(MTOT * DIM / 4) / 256, 256>>>(X, Xb, DIM);
    conv_wt<1><<<(DIM * DIM) / 256, 256>>>(Wq, Wqs);
    conv_wt<1><<<(DIM * DIM) / 256, 256>>>(Wk, Wks);
    conv_wt<0><<<(DIM * DIM) / 256, 256>>>(Wv, Wvs);

    // Projections: Q = X@Wq+bq, K = X@Wk+bk   (M=16384, N=512, K'=1536)
    gemm_mma<1><<<dim3(4, 128, 1), 256, smemBytes>>>(Xa, Wqs, bq, Qf, DIM, KP_PROJ, 0, 0, 0);
    gemm_mma<1><<<dim3(4, 128, 1), 256, smemBytes>>>(Xa, Wks, bk, Kf, DIM, KP_PROJ, 0, 0, 0);
    // V^T = Wv^T @ X^T + bv (row bias)       (M=512, N=16384, K'=1536)
    gemm_mma<2><<<dim3(128, 4, 1), 256, smemBytes>>>(Wvs, Xb, bv, Vtf, MTOT, KP_PROJ, 0, 0, 0);

    // Re-split GEMM outputs for the attention GEMMs
    conv_split<0><<<(MTOT * DIM / 4) / 256, 256>>>(Qf, Qa, DIM);
    conv_split<1><<<(MTOT * DIM / 4) / 256, 256>>>(Kf, Kb, DIM);
    conv_vt<<<(DIM * MTOT / 4) / 256, 256>>>(Vtf, Vtb);

    // Scores: S[b] = Q[b] @ K[b]^T          (M=N=2048, K'=1536, batched)
    gemm_mma<0><<<dim3(16, 16, 8), 256, smemBytes>>>(
        Qa, Kb, nullptr, S, SEQ, KP_PROJ,
        (long)SEQ * KP_PROJ, (long)SEQ * KP_PROJ, (long)SEQ * SEQ);

    // Softmax + split P
    softmax_split<<<MTOT, 256>>>(S, Ps);

    // Out: O[b] = P[b] @ V[b]               (M=2048, N=512, K'=6144, batched)
    gemm_mma<0><<<dim3(4, 16, 8), 256, smemBytes>>>(
        Ps, Vtb, nullptr, out, DIM, KP_PV,
        (long)SEQ * KP_PV, (long)DIM * KP_PV, (long)SEQ * DIM);
}

// round 9
// speedup vs baseline: 2.7519x; 1.0075x over previous
#include <cuda_runtime.h>
#include <cuda_bf16.h>
#include <cstdint>
#include <math.h>

#define SEQ 2048
#define BATCH 8
#define DIM 512
#define MTOT (BATCH*SEQ)      // 16384

// ---------------------------------------------------------------------------
// Scratch (allocation-free __device__ globals) — all splits stored [hi|lo]
// ---------------------------------------------------------------------------
__device__ __nv_bfloat16 g_Xs [(size_t)MTOT*2*DIM];     // X  [16384, 1024]
__device__ __nv_bfloat16 g_Wqs[(size_t)DIM*2*DIM];      // Wq^T [512, 1024]
__device__ __nv_bfloat16 g_Wks[(size_t)DIM*2*DIM];
__device__ __nv_bfloat16 g_Wvs[(size_t)DIM*2*DIM];
__device__ __nv_bfloat16 g_Qs [(size_t)MTOT*2*DIM];     // Q  [16384, 1024]
__device__ __nv_bfloat16 g_Ks [(size_t)MTOT*2*DIM];
__device__ __nv_bfloat16 g_Vts[(size_t)BATCH*DIM*2*SEQ];// V^T [8][512][4096]
__device__ float         g_S  [(size_t)BATCH*SEQ*SEQ];  // scores fp32
__device__ __nv_bfloat16 g_Ps [(size_t)MTOT*2*SEQ];     // probs [16384, 4096]

// ---------------------------------------------------------------------------
// Helpers
// ---------------------------------------------------------------------------
__device__ __forceinline__ uint32_t smem_u32(const void* p) {
    uint32_t a;
    asm("{ .reg .u64 t; cvta.to.shared.u64 t, %1; cvt.u32.u64 %0, t; }"
        : "=r"(a) : "l"(p));
    return a;
}
__device__ __forceinline__ void cp_async16(uint32_t saddr, const void* gaddr) {
    asm volatile("cp.async.cg.shared.global [%0], [%1], 16;"
                 :: "r"(saddr), "l"(gaddr) : "memory");
}
__device__ __forceinline__ void ldsm_x4(uint32_t& r0, uint32_t& r1,
                                        uint32_t& r2, uint32_t& r3, uint32_t a) {
    asm volatile("ldmatrix.sync.aligned.m8n8.x4.shared.b16 {%0,%1,%2,%3}, [%4];"
                 : "=r"(r0), "=r"(r1), "=r"(r2), "=r"(r3) : "r"(a));
}
__device__ __forceinline__ void mma_bf16(float* d, const uint32_t* a,
                                         const uint32_t* b) {
    asm volatile("mma.sync.aligned.m16n8k16.row.col.f32.bf16.bf16.f32 "
                 "{%0,%1,%2,%3}, {%4,%5,%6,%7}, {%8,%9}, {%0,%1,%2,%3};"
                 : "+f"(d[0]), "+f"(d[1]), "+f"(d[2]), "+f"(d[3])
                 : "r"(a[0]), "r"(a[1]), "r"(a[2]), "r"(a[3]),
                   "r"(b[0]), "r"(b[1]));
}
__device__ __forceinline__ void split2(float x, __nv_bfloat16& h, __nv_bfloat16& l) {
    h = __float2bfloat16(x);
    l = __float2bfloat16(x - __bfloat162float(h));
}
__device__ __forceinline__ uint2 pack4(__nv_bfloat16 a, __nv_bfloat16 b,
                                       __nv_bfloat16 c, __nv_bfloat16 d) {
    __nv_bfloat162 p0; p0.x = a; p0.y = b;
    __nv_bfloat162 p1; p1.x = c; p1.y = d;
    uint2 u; u.x = *(uint32_t*)&p0; u.y = *(uint32_t*)&p1;
    return u;
}
__device__ __forceinline__ uint32_t packbf2(__nv_bfloat16 a, __nv_bfloat16 b) {
    __nv_bfloat162 p; p.x = a; p.y = b;
    return *(uint32_t*)&p;
}

// ---------------------------------------------------------------------------
// bf16 mma.sync GEMM with logical->physical K-segment remap.
// Logical K' = 3*cps*64; physical storage = 2 segments [hi|lo].
// BM=BN=128, K-chunk=64 bf16 (128B SW128 rows), 256 thr / 8 warps,
// warp tile 64x32, 3-stage cp.async pipeline.
// EPI: 0 = fp32 out, no bias
//      1 = split bf16 out [row*1024 + col | +512], column bias
//      2 = split bf16 V^T out (batch-segmented cols), row bias
// ---------------------------------------------------------------------------
__device__ __forceinline__ const char* chunk_ptr(
    const char* base, int c, int cps, int cps2,
    int m0_, int m1_, int m2_)
{
    int seg = (c >= cps) + (c >= cps2);
    int off = c - seg * cps;
    int m = (seg == 0) ? m0_ : ((seg == 1) ? m1_ : m2_);
    return base + (size_t)(m * cps + off) * 128;
}

__device__ __forceinline__ void load_chunk(
    uint32_t sdst, const char* Ac, const char* Bc,
    int ld_r, int ld_c, size_t ldab)
{
#pragma unroll
    for (int i = 0; i < 4; i++) {
        int r = ld_r + i * 32;
        uint32_t so = r * 128 + ((ld_c ^ (r & 7)) * 16);
        cp_async16(sdst + so,         Ac + (size_t)r * ldab + ld_c * 16);
        cp_async16(sdst + 16384 + so, Bc + (size_t)r * ldab + ld_c * 16);
    }
}

template <int EPI>
__global__ void __launch_bounds__(256, 2) gemm_mma(
    const __nv_bfloat16* __restrict__ A, const __nv_bfloat16* __restrict__ B,
    const float* __restrict__ bias, void* __restrict__ Cv,
    int ldc, int NC, int cps,
    int mA0, int mA1, int mA2, int mB0, int mB1, int mB2,
    int ldabBytes, long sA, long sB, long sC)
{
    extern __shared__ __align__(16) char smem_raw[];
    uint32_t sraw = smem_u32(smem_raw);
    uint32_t sb = (sraw + 1023u) & ~1023u;   // 3 stages x (16KB A + 16KB B)

    const int tid = threadIdx.x;
    const int wid = tid >> 5, lid = tid & 31;
    const int wm = wid & 1;            // m-warp 0..1
    const int wn = wid >> 1;           // n-warp 0..3

    const int m0 = blockIdx.y * 128;
    const int n0 = blockIdx.x * 128;

    const char* Abase = (const char*)A + (size_t)blockIdx.z * sA * 2 +
                        (size_t)m0 * ldabBytes;
    const char* Bbase = (const char*)B + (size_t)blockIdx.z * sB * 2 +
                        (size_t)n0 * ldabBytes;
    const size_t ldab = (size_t)ldabBytes;
    const int cps2 = cps * 2;

    const int ld_r = tid >> 3;         // row 0..31, step 32
    const int ld_c = tid & 7;          // 16B chunk 0..7

    const int a_r = wm * 64 + ((lid >> 3) & 1) * 8 + (lid & 7);
    const int a_hi = lid >> 4;
    const int b_n = wn * 32 + ((lid >> 4) & 1) * 8 + (lid & 7);
    const int b_hi = (lid >> 3) & 1;

    float acc[4][4][4];
#pragma unroll
    for (int i = 0; i < 4; i++)
#pragma unroll
        for (int j = 0; j < 4; j++)
#pragma unroll
            for (int r = 0; r < 4; r++) acc[i][j][r] = 0.0f;

    // ---- prologue: stage chunks 0,1
#pragma unroll
    for (int p = 0; p < 2; p++) {
        if (p < NC)
            load_chunk(sb + p * 32768,
                       chunk_ptr(Abase, p, cps, cps2, mA0, mA1, mA2),
                       chunk_ptr(Bbase, p, cps, cps2, mB0, mB1, mB2),
                       ld_r, ld_c, ldab);
        asm volatile("cp.async.commit_group;" ::: "memory");
    }

    int buf = 0, nb = 2;
    for (int c = 0; c < NC; c++) {
        if (c + 2 < NC)
            load_chunk(sb + nb * 32768,
                       chunk_ptr(Abase, c + 2, cps, cps2, mA0, mA1, mA2),
                       chunk_ptr(Bbase, c + 2, cps, cps2, mB0, mB1, mB2),
                       ld_r, ld_c, ldab);
        asm volatile("cp.async.commit_group;" ::: "memory");
        asm volatile("cp.async.wait_group 2;" ::: "memory");
        __syncthreads();

        const uint32_t sa = sb + buf * 32768;
        const uint32_t sbb = sa + 16384;
#pragma unroll
        for (int ks = 0; ks < 4; ks++) {
            uint32_t af[4][4], bf[4][2];
#pragma unroll
            for (int mf = 0; mf < 4; mf++) {
                int r = a_r + mf * 16;
                uint32_t ad = sa + r * 128 + (((ks * 2 + a_hi) ^ (r & 7)) * 16);
                ldsm_x4(af[mf][0], af[mf][1], af[mf][2], af[mf][3], ad);
            }
#pragma unroll
            for (int p = 0; p < 2; p++) {
                int n = b_n + p * 16;
                uint32_t bd = sbb + n * 128 + (((ks * 2 + b_hi) ^ (n & 7)) * 16);
                ldsm_x4(bf[2 * p][0], bf[2 * p][1],
                        bf[2 * p + 1][0], bf[2 * p + 1][1], bd);
            }
#pragma unroll
            for (int mf = 0; mf < 4; mf++)
#pragma unroll
                for (int nf = 0; nf < 4; nf++)
                    mma_bf16(acc[mf][nf], af[mf], bf[nf]);
        }
        __syncthreads();
        buf = (buf == 2) ? 0 : buf + 1;
        nb  = (nb == 2) ? 0 : nb + 1;
    }

    // ---- epilogue (registers only; no smem)
    const int g = lid >> 2, t = lid & 3;
#pragma unroll
    for (int mf = 0; mf < 4; mf++) {
#pragma unroll
        for (int half = 0; half < 2; half++) {
            const int row = m0 + wm * 64 + mf * 16 + g + half * 8;
            float brow = (EPI == 2) ? bias[row] : 0.0f;
#pragma unroll
            for (int nf = 0; nf < 4; nf++) {
                const int col = n0 + wn * 32 + nf * 8 + t * 2;
                float vx = acc[mf][nf][half * 2 + 0];
                float vy = acc[mf][nf][half * 2 + 1];
                if (EPI == 0) {
                    float* C = (float*)Cv + (size_t)blockIdx.z * sC;
                    float2 v; v.x = vx; v.y = vy;
                    *(float2*)(C + (size_t)row * ldc + col) = v;
                } else if (EPI == 1) {
                    __nv_bfloat16* C = (__nv_bfloat16*)Cv;
                    vx += bias[col]; vy += bias[col + 1];
                    __nv_bfloat16 hx, lx, hy, ly;
                    split2(vx, hx, lx); split2(vy, hy, ly);
                    size_t base = (size_t)row * 1024 + col;
                    *(uint32_t*)(C + base)       = packbf2(hx, hy);
                    *(uint32_t*)(C + base + 512) = packbf2(lx, ly);
                } else {
                    // V^T split, batch-segmented columns
                    __nv_bfloat16* C = (__nv_bfloat16*)Cv;
                    vx += brow; vy += brow;
                    __nv_bfloat16 hx, lx, hy, ly;
                    split2(vx, hx, lx); split2(vy, hy, ly);
                    int b = col >> 11, ml = col & 2047;
                    size_t base = ((size_t)b * DIM + row) * 4096 + ml;
                    *(uint32_t*)(C + base)        = packbf2(hx, hy);
                    *(uint32_t*)(C + base + 2048) = packbf2(lx, ly);
                }
            }
        }
    }
}

// ---------------------------------------------------------------------------
// fp32 [R,512] -> bf16 [R, hi(512)|lo(512)]
// ---------------------------------------------------------------------------
__global__ void __launch_bounds__(256) conv_split(
    const float* __restrict__ in, __nv_bfloat16* __restrict__ out)
{
    int idx = blockIdx.x * 256 + threadIdx.x;         // float4 index
    int row = idx >> 7, c4 = idx & 127;
    float4 v = ((const float4*)in)[idx];
    __nv_bfloat16 h0, h1, h2, h3, l0, l1, l2, l3;
    split2(v.x, h0, l0); split2(v.y, h1, l1);
    split2(v.z, h2, l2); split2(v.w, h3, l3);
    size_t ob = (size_t)row * 1024 + c4 * 4;
    *(uint2*)(out + ob)       = pack4(h0, h1, h2, h3);
    *(uint2*)(out + ob + 512) = pack4(l0, l1, l2, l3);
}

// W [512,512] -> Ws [512 n-rows, hi(512)|lo(512)] transposed split
__global__ void __launch_bounds__(256) conv_wt(
    const float* __restrict__ W, __nv_bfloat16* __restrict__ out)
{
    int t = blockIdx.x * 256 + threadIdx.x;           // 512*512
    int n = t >> 9, k = t & 511;
    __nv_bfloat16 h, l;
    split2(W[(size_t)k * 512 + n], h, l);
    size_t ob = (size_t)n * 1024;
    out[ob + k]       = h;
    out[ob + 512 + k] = l;
}

// ---------------------------------------------------------------------------
// Softmax over 2048-wide rows, fused split-bf16 [hi(2048)|lo(2048)] output
// ---------------------------------------------------------------------------
__global__ void __launch_bounds__(256) softmax_split(
    const float* __restrict__ S, __nv_bfloat16* __restrict__ Ps)
{
    const float* p = S + (size_t)blockIdx.x * SEQ;
    const int tid = threadIdx.x;

    float4 v0 = ((const float4*)p)[tid];
    float4 v1 = ((const float4*)p)[tid + 256];

    float m = fmaxf(fmaxf(fmaxf(v0.x, v0.y), fmaxf(v0.z, v0.w)),
                    fmaxf(fmaxf(v1.x, v1.y), fmaxf(v1.z, v1.w)));
    __shared__ float red[256];
    red[tid] = m; __syncthreads();
    for (int s = 128; s >= 1; s >>= 1) {
        if (tid < s) red[tid] = fmaxf(red[tid], red[tid + s]);
        __syncthreads();
    }
    float rowmax = red[0]; __syncthreads();

    v0.x = __expf(v0.x - rowmax); v0.y = __expf(v0.y - rowmax);
    v0.z = __expf(v0.z - rowmax); v0.w = __expf(v0.w - rowmax);
    v1.x = __expf(v1.x - rowmax); v1.y = __expf(v1.y - rowmax);
    v1.z = __expf(v1.z - rowmax); v1.w = __expf(v1.w - rowmax);

    float sum = (v0.x + v0.y + v0.z + v0.w) + (v1.x + v1.y + v1.z + v1.w);
    red[tid] = sum; __syncthreads();
    for (int s = 128; s >= 1; s >>= 1) {
        if (tid < s) red[tid] += red[tid + s];
        __syncthreads();
    }
    float inv = 1.0f / red[0];

    size_t ob = (size_t)blockIdx.x * 4096;
    __nv_bfloat16 h0, h1, h2, h3, l0, l1, l2, l3;

    split2(v0.x * inv, h0, l0); split2(v0.y * inv, h1, l1);
    split2(v0.z * inv, h2, l2); split2(v0.w * inv, h3, l3);
    {
        size_t c = ob + tid * 4;
        *(uint2*)(Ps + c)        = pack4(h0, h1, h2, h3);
        *(uint2*)(Ps + c + 2048) = pack4(l0, l1, l2, l3);
    }
    split2(v1.x * inv, h0, l0); split2(v1.y * inv, h1, l1);
    split2(v1.z * inv, h2, l2); split2(v1.w * inv, h3, l3);
    {
        size_t c = ob + 1024 + tid * 4;
        *(uint2*)(Ps + c)        = pack4(h0, h1, h2, h3);
        *(uint2*)(Ps + c + 2048) = pack4(l0, l1, l2, l3);
    }
}

// ---------------------------------------------------------------------------
// kernel_launch: inputs = X, Wq, bq, Wk, bk, Wv, bv
// ---------------------------------------------------------------------------
extern "C" void kernel_launch(void* const* d_in, const int* in_sizes, int n_in,
                              void* d_out, int out_size)
{
    const float* X  = (const float*)d_in[0];
    const float* Wq = (const float*)d_in[1];
    const float* bq = (const float*)d_in[2];
    const float* Wk = (const float*)d_in[3];
    const float* bk = (const float*)d_in[4];
    const float* Wv = (const float*)d_in[5];
    const float* bv = (const float*)d_in[6];
    float* out = (float*)d_out;

    __nv_bfloat16 *Xs, *Wqs, *Wks, *Wvs, *Qs, *Ks, *Vts, *Ps;
    float *S;
    cudaGetSymbolAddress((void**)&Xs,  g_Xs);
    cudaGetSymbolAddress((void**)&Wqs, g_Wqs);
    cudaGetSymbolAddress((void**)&Wks, g_Wks);
    cudaGetSymbolAddress((void**)&Wvs, g_Wvs);
    cudaGetSymbolAddress((void**)&Qs,  g_Qs);
    cudaGetSymbolAddress((void**)&Ks,  g_Ks);
    cudaGetSymbolAddress((void**)&Vts, g_Vts);
    cudaGetSymbolAddress((void**)&S,   g_S);
    cudaGetSymbolAddress((void**)&Ps,  g_Ps);

    const int smemBytes = 1024 + 3 * 32768;  // pad + 3 stages x (A+B)
    cudaFuncSetAttribute(gemm_mma<0>, cudaFuncAttributeMaxDynamicSharedMemorySize, smemBytes);
    cudaFuncSetAttribute(gemm_mma<1>, cudaFuncAttributeMaxDynamicSharedMemorySize, smemBytes);
    cudaFuncSetAttribute(gemm_mma<2>, cudaFuncAttributeMaxDynamicSharedMemorySize, smemBytes);

    // Split conversions (X once, three weights)
    conv_split<<<(MTOT * DIM / 4) / 256, 256>>>(X, Xs);
    conv_wt<<<(DIM * DIM) / 256, 256>>>(Wq, Wqs);
    conv_wt<<<(DIM * DIM) / 256, 256>>>(Wk, Wks);
    conv_wt<<<(DIM * DIM) / 256, 256>>>(Wv, Wvs);

    // Q = X@Wq+bq, K = X@Wk+bk  (M=16384, N=512, K'=1536, cps=8)
    // A pattern (hi,lo,hi), B pattern (hi,hi,lo); split-bf16 epilogue
    gemm_mma<1><<<dim3(4, 128, 1), 256, smemBytes>>>(
        Xs, Wqs, bq, Qs, 0, 24, 8, 0, 1, 0, 0, 0, 1, 2048, 0, 0, 0);
    gemm_mma<1><<<dim3(4, 128, 1), 256, smemBytes>>>(
        Xs, Wks, bk, Ks, 0, 24, 8, 0, 1, 0, 0, 0, 1, 2048, 0, 0, 0);
    // V^T = Wv^T @ X^T + bv(row)  (M=512, N=16384) -> batch-segmented split
    gemm_mma<2><<<dim3(128, 4, 1), 256, smemBytes>>>(
        Wvs, Xs, bv, Vts, 0, 24, 8, 0, 1, 0, 0, 0, 1, 2048, 0, 0, 0);

    // Scores: S[b] = Q[b] @ K[b]^T  (M=N=2048, K'=1536, cps=8, batched)
    gemm_mma<0><<<dim3(16, 16, 8), 256, smemBytes>>>(
        Qs, Ks, nullptr, S, SEQ, 24, 8, 0, 1, 0, 0, 0, 1, 2048,
        (long)SEQ * 1024, (long)SEQ * 1024, (long)SEQ * SEQ);

    // Softmax + split P
    softmax_split<<<MTOT, 256>>>(S, Ps);

    // Out: O[b] = P[b] @ V[b]  (M=2048, N=512, K'=6144, cps=32, batched)
    gemm_mma<0><<<dim3(4, 16, 8), 256, smemBytes>>>(
        Ps, Vts, nullptr, out, DIM, 96, 32, 0, 1, 0, 0, 0, 1, 8192,
        (long)SEQ * 4096, (long)DIM * 4096, (long)SEQ * DIM);
}

// round 11
// speedup vs baseline: 2.7981x; 1.0168x over previous
#include <cuda_runtime.h>
#include <cuda_bf16.h>
#include <cstdint>
#include <math.h>

#define SEQ 2048
#define BATCH 8
#define DIM 512
#define MTOT (BATCH*SEQ)      // 16384

// ---------------------------------------------------------------------------
// Scratch (allocation-free __device__ globals) — all splits stored [hi|lo]
// ---------------------------------------------------------------------------
__device__ __nv_bfloat16 g_Xs [(size_t)MTOT*2*DIM];     // X  [16384, 1024]
__device__ __nv_bfloat16 g_Wqs[(size_t)DIM*2*DIM];      // Wq^T [512, 1024]
__device__ __nv_bfloat16 g_Wks[(size_t)DIM*2*DIM];
__device__ __nv_bfloat16 g_Wvs[(size_t)DIM*2*DIM];
__device__ __nv_bfloat16 g_Qs [(size_t)MTOT*2*DIM];     // Q  [16384, 1024]
__device__ __nv_bfloat16 g_Ks [(size_t)MTOT*2*DIM];
__device__ __nv_bfloat16 g_Vts[(size_t)BATCH*DIM*2*SEQ];// V^T [8][512][4096]
__device__ float         g_S  [(size_t)BATCH*SEQ*SEQ];  // scores fp32
__device__ __nv_bfloat16 g_Ps [(size_t)MTOT*2*SEQ];     // probs [16384, 4096]

// ---------------------------------------------------------------------------
// Helpers
// ---------------------------------------------------------------------------
__device__ __forceinline__ uint32_t smem_u32(const void* p) {
    uint32_t a;
    asm("{ .reg .u64 t; cvta.to.shared.u64 t, %1; cvt.u32.u64 %0, t; }"
        : "=r"(a) : "l"(p));
    return a;
}
__device__ __forceinline__ void cp_async16(uint32_t saddr, const void* gaddr) {
    asm volatile("cp.async.cg.shared.global [%0], [%1], 16;"
                 :: "r"(saddr), "l"(gaddr) : "memory");
}
__device__ __forceinline__ void ldsm_x4(uint32_t& r0, uint32_t& r1,
                                        uint32_t& r2, uint32_t& r3, uint32_t a) {
    asm volatile("ldmatrix.sync.aligned.m8n8.x4.shared.b16 {%0,%1,%2,%3}, [%4];"
                 : "=r"(r0), "=r"(r1), "=r"(r2), "=r"(r3) : "r"(a));
}
__device__ __forceinline__ void mma_bf16(float* d, const uint32_t* a,
                                         const uint32_t* b) {
    asm volatile("mma.sync.aligned.m16n8k16.row.col.f32.bf16.bf16.f32 "
                 "{%0,%1,%2,%3}, {%4,%5,%6,%7}, {%8,%9}, {%0,%1,%2,%3};"
                 : "+f"(d[0]), "+f"(d[1]), "+f"(d[2]), "+f"(d[3])
                 : "r"(a[0]), "r"(a[1]), "r"(a[2]), "r"(a[3]),
                   "r"(b[0]), "r"(b[1]));
}
__device__ __forceinline__ void split2(float x, __nv_bfloat16& h, __nv_bfloat16& l) {
    h = __float2bfloat16(x);
    l = __float2bfloat16(x - __bfloat162float(h));
}
__device__ __forceinline__ uint2 pack4(__nv_bfloat16 a, __nv_bfloat16 b,
                                       __nv_bfloat16 c, __nv_bfloat16 d) {
    __nv_bfloat162 p0; p0.x = a; p0.y = b;
    __nv_bfloat162 p1; p1.x = c; p1.y = d;
    uint2 u; u.x = *(uint32_t*)&p0; u.y = *(uint32_t*)&p1;
    return u;
}
__device__ __forceinline__ uint32_t packbf2(__nv_bfloat16 a, __nv_bfloat16 b) {
    __nv_bfloat162 p; p.x = a; p.y = b;
    return *(uint32_t*)&p;
}

// ---------------------------------------------------------------------------
// bf16 mma.sync GEMM with logical->physical K-segment remap.
// Logical K' = 3*cps*64; physical storage = 2 segments [hi|lo].
// BM=BN=128, K-chunk=64 bf16, 256 thr / 8 warps, warp tile 64x32,
// 3-stage cp.async pipeline, ONE barrier per chunk, A-frag double buffer.
// EPI: 0 = fp32 out, no bias
//      1 = split bf16 out [row*1024 + col | +512], column bias (z selects Q/K)
//      2 = split bf16 V^T out (batch-segmented cols), row bias
// ---------------------------------------------------------------------------
__device__ __forceinline__ const char* chunk_ptr(
    const char* base, int c, int cps, int cps2,
    int m0_, int m1_, int m2_)
{
    int seg = (c >= cps) + (c >= cps2);
    int off = c - seg * cps;
    int m = (seg == 0) ? m0_ : ((seg == 1) ? m1_ : m2_);
    return base + (size_t)(m * cps + off) * 128;
}

__device__ __forceinline__ void load_chunk(
    uint32_t sdst, const char* Ac, const char* Bc,
    int ld_r, int ld_c, size_t ldab)
{
#pragma unroll
    for (int i = 0; i < 4; i++) {
        int r = ld_r + i * 32;
        uint32_t so = r * 128 + ((ld_c ^ (r & 7)) * 16);
        cp_async16(sdst + so,         Ac + (size_t)r * ldab + ld_c * 16);
        cp_async16(sdst + 16384 + so, Bc + (size_t)r * ldab + ld_c * 16);
    }
}

template <int EPI>
__global__ void __launch_bounds__(256, 2) gemm_mma(
    const __nv_bfloat16* __restrict__ A, const __nv_bfloat16* __restrict__ B,
    const float* __restrict__ bias, void* __restrict__ Cv,
    const __nv_bfloat16* __restrict__ B2, const float* __restrict__ bias2,
    void* __restrict__ Cv2,
    int ldc, int NC, int cps,
    int mA0, int mA1, int mA2, int mB0, int mB1, int mB2,
    int ldabBytes, long sA, long sB, long sC)
{
    extern __shared__ __align__(16) char smem_raw[];
    uint32_t sraw = smem_u32(smem_raw);
    uint32_t sb = (sraw + 1023u) & ~1023u;   // 3 stages x (16KB A + 16KB B)

    const int tid = threadIdx.x;
    const int wid = tid >> 5, lid = tid & 31;
    const int wm = wid & 1;            // m-warp 0..1
    const int wn = wid >> 1;           // n-warp 0..3

    if (EPI == 1 && blockIdx.z == 1) { B = B2; bias = bias2; Cv = Cv2; }

    const int m0 = blockIdx.y * 128;
    const int n0 = blockIdx.x * 128;

    const char* Abase = (const char*)A + (size_t)blockIdx.z * sA * 2 +
                        (size_t)m0 * ldabBytes;
    const char* Bbase = (const char*)B + (size_t)blockIdx.z * sB * 2 +
                        (size_t)n0 * ldabBytes;
    const size_t ldab = (size_t)ldabBytes;
    const int cps2 = cps * 2;

    const int ld_r = tid >> 3;         // row 0..31, step 32
    const int ld_c = tid & 7;          // 16B chunk 0..7

    const int a_r = wm * 64 + ((lid >> 3) & 1) * 8 + (lid & 7);
    const int a_hi = lid >> 4;
    const int b_n = wn * 32 + ((lid >> 4) & 1) * 8 + (lid & 7);
    const int b_hi = (lid >> 3) & 1;

    float acc[4][4][4];
#pragma unroll
    for (int i = 0; i < 4; i++)
#pragma unroll
        for (int j = 0; j < 4; j++)
#pragma unroll
            for (int r = 0; r < 4; r++) acc[i][j][r] = 0.0f;

    // ---- prologue: stage chunks 0,1
#pragma unroll
    for (int p = 0; p < 2; p++) {
        if (p < NC)
            load_chunk(sb + p * 32768,
                       chunk_ptr(Abase, p, cps, cps2, mA0, mA1, mA2),
                       chunk_ptr(Bbase, p, cps, cps2, mB0, mB1, mB2),
                       ld_r, ld_c, ldab);
        asm volatile("cp.async.commit_group;" ::: "memory");
    }

    int buf = 0;
    for (int c = 0; c < NC; c++) {
        asm volatile("cp.async.wait_group 1;" ::: "memory");
        __syncthreads();   // chunk c landed; all warps done reading buf (c-1)%3

        // issue loads for chunk c+2 into buffer (c+2)%3 == (c-1)%3 (now free)
        {
            int nb = buf + 2; if (nb >= 3) nb -= 3;
            if (c + 2 < NC)
                load_chunk(sb + nb * 32768,
                           chunk_ptr(Abase, c + 2, cps, cps2, mA0, mA1, mA2),
                           chunk_ptr(Bbase, c + 2, cps, cps2, mB0, mB1, mB2),
                           ld_r, ld_c, ldab);
            asm volatile("cp.async.commit_group;" ::: "memory");
        }

        const uint32_t sa = sb + buf * 32768;
        const uint32_t sbb = sa + 16384;

        uint32_t af[2][4][4], bfr[4][2];
        // preload A fragments for ks=0
#pragma unroll
        for (int mf = 0; mf < 4; mf++) {
            int r = a_r + mf * 16;
            uint32_t ad = sa + r * 128 + ((a_hi ^ (r & 7)) * 16);
            ldsm_x4(af[0][mf][0], af[0][mf][1], af[0][mf][2], af[0][mf][3], ad);
        }
#pragma unroll
        for (int ks = 0; ks < 4; ks++) {
            const int cur = ks & 1;
#pragma unroll
            for (int p = 0; p < 2; p++) {
                int n = b_n + p * 16;
                uint32_t bd = sbb + n * 128 + (((ks * 2 + b_hi) ^ (n & 7)) * 16);
                ldsm_x4(bfr[2 * p][0], bfr[2 * p][1],
                        bfr[2 * p + 1][0], bfr[2 * p + 1][1], bd);
            }
            if (ks < 3) {
#pragma unroll
                for (int mf = 0; mf < 4; mf++) {
                    int r = a_r + mf * 16;
                    uint32_t ad = sa + r * 128 +
                                  ((((ks + 1) * 2 + a_hi) ^ (r & 7)) * 16);
                    ldsm_x4(af[cur ^ 1][mf][0], af[cur ^ 1][mf][1],
                            af[cur ^ 1][mf][2], af[cur ^ 1][mf][3], ad);
                }
            }
#pragma unroll
            for (int mf = 0; mf < 4; mf++)
#pragma unroll
                for (int nf = 0; nf < 4; nf++)
                    mma_bf16(acc[mf][nf], af[cur][mf], bfr[nf]);
        }
        buf = buf + 1; if (buf == 3) buf = 0;
    }

    // ---- epilogue (registers only; no smem)
    const int g = lid >> 2, t = lid & 3;
#pragma unroll
    for (int mf = 0; mf < 4; mf++) {
#pragma unroll
        for (int half = 0; half < 2; half++) {
            const int row = m0 + wm * 64 + mf * 16 + g + half * 8;
            float brow = (EPI == 2) ? bias[row] : 0.0f;
#pragma unroll
            for (int nf = 0; nf < 4; nf++) {
                const int col = n0 + wn * 32 + nf * 8 + t * 2;
                float vx = acc[mf][nf][half * 2 + 0];
                float vy = acc[mf][nf][half * 2 + 1];
                if (EPI == 0) {
                    float* C = (float*)Cv + (size_t)blockIdx.z * sC;
                    float2 v; v.x = vx; v.y = vy;
                    *(float2*)(C + (size_t)row * ldc + col) = v;
                } else if (EPI == 1) {
                    __nv_bfloat16* C = (__nv_bfloat16*)Cv;
                    vx += bias[col]; vy += bias[col + 1];
                    __nv_bfloat16 hx, lx, hy, ly;
                    split2(vx, hx, lx); split2(vy, hy, ly);
                    size_t base = (size_t)row * 1024 + col;
                    *(uint32_t*)(C + base)       = packbf2(hx, hy);
                    *(uint32_t*)(C + base + 512) = packbf2(lx, ly);
                } else {
                    // V^T split, batch-segmented columns
                    __nv_bfloat16* C = (__nv_bfloat16*)Cv;
                    vx += brow; vy += brow;
                    __nv_bfloat16 hx, lx, hy, ly;
                    split2(vx, hx, lx); split2(vy, hy, ly);
                    int b = col >> 11, ml = col & 2047;
                    size_t base = ((size_t)b * DIM + row) * 4096 + ml;
                    *(uint32_t*)(C + base)        = packbf2(hx, hy);
                    *(uint32_t*)(C + base + 2048) = packbf2(lx, ly);
                }
            }
        }
    }
}

// ---------------------------------------------------------------------------
// fp32 [R,512] -> bf16 [R, hi(512)|lo(512)]
// ---------------------------------------------------------------------------
__global__ void __launch_bounds__(256) conv_split(
    const float* __restrict__ in, __nv_bfloat16* __restrict__ out)
{
    int idx = blockIdx.x * 256 + threadIdx.x;         // float4 index
    int row = idx >> 7, c4 = idx & 127;
    float4 v = ((const float4*)in)[idx];
    __nv_bfloat16 h0, h1, h2, h3, l0, l1, l2, l3;
    split2(v.x, h0, l0); split2(v.y, h1, l1);
    split2(v.z, h2, l2); split2(v.w, h3, l3);
    size_t ob = (size_t)row * 1024 + c4 * 4;
    *(uint2*)(out + ob)       = pack4(h0, h1, h2, h3);
    *(uint2*)(out + ob + 512) = pack4(l0, l1, l2, l3);
}

// W [512,512] -> Ws [512 n-rows, hi(512)|lo(512)] transposed split.
// 32x32 tile transpose via smem: coalesced reads AND writes.
__global__ void __launch_bounds__(256) conv_wt(
    const float* __restrict__ W, __nv_bfloat16* __restrict__ out)
{
    __shared__ float t[32][33];
    const int tx = threadIdx.x & 31, ty = threadIdx.x >> 5;   // 32 x 8
    const int k0 = (blockIdx.x & 15) * 32, n0 = (blockIdx.x >> 4) * 32;
#pragma unroll
    for (int i = 0; i < 32; i += 8)
        t[ty + i][tx] = W[(size_t)(k0 + ty + i) * 512 + (n0 + tx)];
    __syncthreads();
#pragma unroll
    for (int i = 0; i < 32; i += 8) {
        float v = t[tx][ty + i];   // = W[k0+tx][n0+ty+i]
        __nv_bfloat16 h, l;
        split2(v, h, l);
        size_t ob = (size_t)(n0 + ty + i) * 1024 + (k0 + tx);
        out[ob]       = h;
        out[ob + 512] = l;
    }
}

// ---------------------------------------------------------------------------
// Softmax over 2048-wide rows, fused split-bf16 [hi(2048)|lo(2048)] output
// ---------------------------------------------------------------------------
__global__ void __launch_bounds__(256) softmax_split(
    const float* __restrict__ S, __nv_bfloat16* __restrict__ Ps)
{
    const float* p = S + (size_t)blockIdx.x * SEQ;
    const int tid = threadIdx.x;
    const int wid = tid >> 5, lid = tid & 31;

    float4 v0 = ((const float4*)p)[tid];
    float4 v1 = ((const float4*)p)[tid + 256];

    __shared__ float red[8];

    float m = fmaxf(fmaxf(fmaxf(v0.x, v0.y), fmaxf(v0.z, v0.w)),
                    fmaxf(fmaxf(v1.x, v1.y), fmaxf(v1.z, v1.w)));
#pragma unroll
    for (int o = 16; o; o >>= 1) m = fmaxf(m, __shfl_xor_sync(~0u, m, o));
    if (lid == 0) red[wid] = m;
    __syncthreads();
    float rowmax = red[0];
#pragma unroll
    for (int i = 1; i < 8; i++) rowmax = fmaxf(rowmax, red[i]);
    __syncthreads();

    v0.x = __expf(v0.x - rowmax); v0.y = __expf(v0.y - rowmax);
    v0.z = __expf(v0.z - rowmax); v0.w = __expf(v0.w - rowmax);
    v1.x = __expf(v1.x - rowmax); v1.y = __expf(v1.y - rowmax);
    v1.z = __expf(v1.z - rowmax); v1.w = __expf(v1.w - rowmax);

    float sum = (v0.x + v0.y + v0.z + v0.w) + (v1.x + v1.y + v1.z + v1.w);
#pragma unroll
    for (int o = 16; o; o >>= 1) sum += __shfl_xor_sync(~0u, sum, o);
    if (lid == 0) red[wid] = sum;
    __syncthreads();
    float tot = 0.0f;
#pragma unroll
    for (int i = 0; i < 8; i++) tot += red[i];
    float inv = 1.0f / tot;

    size_t ob = (size_t)blockIdx.x * 4096;
    __nv_bfloat16 h0, h1, h2, h3, l0, l1, l2, l3;

    split2(v0.x * inv, h0, l0); split2(v0.y * inv, h1, l1);
    split2(v0.z * inv, h2, l2); split2(v0.w * inv, h3, l3);
    {
        size_t c = ob + tid * 4;
        *(uint2*)(Ps + c)        = pack4(h0, h1, h2, h3);
        *(uint2*)(Ps + c + 2048) = pack4(l0, l1, l2, l3);
    }
    split2(v1.x * inv, h0, l0); split2(v1.y * inv, h1, l1);
    split2(v1.z * inv, h2, l2); split2(v1.w * inv, h3, l3);
    {
        size_t c = ob + 1024 + tid * 4;
        *(uint2*)(Ps + c)        = pack4(h0, h1, h2, h3);
        *(uint2*)(Ps + c + 2048) = pack4(l0, l1, l2, l3);
    }
}

// ---------------------------------------------------------------------------
// kernel_launch: inputs = X, Wq, bq, Wk, bk, Wv, bv
// ---------------------------------------------------------------------------
extern "C" void kernel_launch(void* const* d_in, const int* in_sizes, int n_in,
                              void* d_out, int out_size)
{
    const float* X  = (const float*)d_in[0];
    const float* Wq = (const float*)d_in[1];
    const float* bq = (const float*)d_in[2];
    const float* Wk = (const float*)d_in[3];
    const float* bk = (const float*)d_in[4];
    const float* Wv = (const float*)d_in[5];
    const float* bv = (const float*)d_in[6];
    float* out = (float*)d_out;

    __nv_bfloat16 *Xs, *Wqs, *Wks, *Wvs, *Qs, *Ks, *Vts, *Ps;
    float *S;
    cudaGetSymbolAddress((void**)&Xs,  g_Xs);
    cudaGetSymbolAddress((void**)&Wqs, g_Wqs);
    cudaGetSymbolAddress((void**)&Wks, g_Wks);
    cudaGetSymbolAddress((void**)&Wvs, g_Wvs);
    cudaGetSymbolAddress((void**)&Qs,  g_Qs);
    cudaGetSymbolAddress((void**)&Ks,  g_Ks);
    cudaGetSymbolAddress((void**)&Vts, g_Vts);
    cudaGetSymbolAddress((void**)&S,   g_S);
    cudaGetSymbolAddress((void**)&Ps,  g_Ps);

    const int smemBytes = 1024 + 3 * 32768;  // pad + 3 stages x (A+B)
    cudaFuncSetAttribute(gemm_mma<0>, cudaFuncAttributeMaxDynamicSharedMemorySize, smemBytes);
    cudaFuncSetAttribute(gemm_mma<1>, cudaFuncAttributeMaxDynamicSharedMemorySize, smemBytes);
    cudaFuncSetAttribute(gemm_mma<2>, cudaFuncAttributeMaxDynamicSharedMemorySize, smemBytes);

    // Launch 0-2: conversions needed by the merged QK projection
    conv_split<<<(MTOT * DIM / 4) / 256, 256>>>(X, Xs);
    conv_wt<<<256, 256>>>(Wq, Wqs);
    conv_wt<<<256, 256>>>(Wk, Wks);

    // Launch 3 (ncu capture slot): merged Q&K projections
    // (M=16384, N=512, K'=1536, cps=8; z=0 -> Q, z=1 -> K)
    gemm_mma<1><<<dim3(4, 128, 2), 256, smemBytes>>>(
        Xs, Wqs, bq, Qs, Wks, bk, Ks,
        0, 24, 8, 0, 1, 0, 0, 0, 1, 2048, 0, 0, 0);

    conv_wt<<<256, 256>>>(Wv, Wvs);

    // V^T = Wv^T @ X^T + bv(row)  (M=512, N=16384) -> batch-segmented split
    gemm_mma<2><<<dim3(128, 4, 1), 256, smemBytes>>>(
        Wvs, Xs, bv, Vts, nullptr, nullptr, nullptr,
        0, 24, 8, 0, 1, 0, 0, 0, 1, 2048, 0, 0, 0);

    // Scores: S[b] = Q[b] @ K[b]^T  (M=N=2048, K'=1536, cps=8, batched)
    gemm_mma<0><<<dim3(16, 16, 8), 256, smemBytes>>>(
        Qs, Ks, nullptr, S, nullptr, nullptr, nullptr,
        SEQ, 24, 8, 0, 1, 0, 0, 0, 1, 2048,
        (long)SEQ * 1024, (long)SEQ * 1024, (long)SEQ * SEQ);

    // Softmax + split P
    softmax_split<<<MTOT, 256>>>(S, Ps);

    // Out: O[b] = P[b] @ V[b]  (M=2048, N=512, K'=6144, cps=32, batched)
    gemm_mma<0><<<dim3(4, 16, 8), 256, smemBytes>>>(
        Ps, Vts, nullptr, out, nullptr, nullptr, nullptr,
        DIM, 96, 32, 0, 1, 0, 0, 0, 1, 8192,
        (long)SEQ * 4096, (long)DIM * 4096, (long)SEQ * DIM);
}